// round 1
// baseline (speedup 1.0000x reference)
#include <cuda_runtime.h>
#include <math.h>

#define N_ROIS 4096
#define N_BANK 8192
#define DIM_IN 2048
#define QDIM   2048
#define LATENT 1024

// ---------------- scratch (static device allocations; no runtime alloc) ----------------
__device__ float g_q1[N_ROIS * LATENT];
__device__ float g_q2[N_ROIS * LATENT];
__device__ float g_k1[N_BANK * LATENT];
__device__ float g_v1[N_BANK * LATENT];
__device__ float g_k2[N_BANK * LATENT];
__device__ float g_v2[N_BANK * LATENT];
__device__ float g_S [N_ROIS * N_BANK];
__device__ float g_f1[N_ROIS * LATENT];
__device__ float g_f2[N_ROIS * LATENT];
__device__ float g_x [N_ROIS * LATENT];

// ---------------- tiled SGEMM: C = alpha * (A @ opB) (+ bias) ----------------
// A: [M,K] row-major.
// TRANSB=true : B is [N,K] row-major (C[m,n] = sum_k A[m,k]*B[n,k])   -> NT
// TRANSB=false: B is [K,N] row-major (C[m,n] = sum_k A[m,k]*B[k,n])   -> NN
// BM=BN=128, BK=8, 256 threads, 8x8 per-thread tile.
template <bool TRANSB, bool HAS_BIAS>
__global__ void __launch_bounds__(256, 2)
sgemm_kernel(const float* __restrict__ A, const float* __restrict__ B,
             const float* __restrict__ bias, float* __restrict__ C,
             int M, int N, int K, float alpha)
{
    constexpr int BM = 128, BN = 128, BK = 8;
    __shared__ float As[BK][BM];
    __shared__ float Bs[BK][BN];

    const int t  = threadIdx.x;
    const int tx = t & 15;   // 0..15 -> N direction (8 cols each)
    const int ty = t >> 4;   // 0..15 -> M direction (8 rows each)
    const int m0 = blockIdx.y * BM;
    const int n0 = blockIdx.x * BN;

    // A tile loader: 128 rows x 8 cols = 256 float4 (one per thread)
    const int arow = t >> 1;
    const int acol = (t & 1) * 4;
    const float* Ap = A + (size_t)(m0 + arow) * K + acol;

    // B tile loader
    int brow, bcol;
    const float* Bp;
    if (TRANSB) {
        brow = t >> 1;          // 0..127 (N direction)
        bcol = (t & 1) * 4;     // K direction
        Bp = B + (size_t)(n0 + brow) * K + bcol;
    } else {
        brow = t >> 5;          // 0..7 (K direction)
        bcol = (t & 31) * 4;    // 0..124 (N direction)
        Bp = B + (size_t)brow * N + n0 + bcol;
    }

    float acc[8][8];
#pragma unroll
    for (int i = 0; i < 8; i++)
#pragma unroll
        for (int j = 0; j < 8; j++) acc[i][j] = 0.f;

    for (int k0 = 0; k0 < K; k0 += BK) {
        float4 av = *(const float4*)(Ap + k0);
        As[acol + 0][arow] = av.x;
        As[acol + 1][arow] = av.y;
        As[acol + 2][arow] = av.z;
        As[acol + 3][arow] = av.w;
        if (TRANSB) {
            float4 bv = *(const float4*)(Bp + k0);
            Bs[bcol + 0][brow] = bv.x;
            Bs[bcol + 1][brow] = bv.y;
            Bs[bcol + 2][brow] = bv.z;
            Bs[bcol + 3][brow] = bv.w;
        } else {
            float4 bv = *(const float4*)(Bp + (size_t)k0 * N);
            *(float4*)&Bs[brow][bcol] = bv;
        }
        __syncthreads();

#pragma unroll
        for (int k = 0; k < BK; k++) {
            float ra[8], rb[8];
#pragma unroll
            for (int i = 0; i < 8; i++) ra[i] = As[k][ty * 8 + i];
#pragma unroll
            for (int j = 0; j < 8; j++) rb[j] = Bs[k][tx * 8 + j];
#pragma unroll
            for (int i = 0; i < 8; i++)
#pragma unroll
                for (int j = 0; j < 8; j++)
                    acc[i][j] = fmaf(ra[i], rb[j], acc[i][j]);
        }
        __syncthreads();
    }

#pragma unroll
    for (int i = 0; i < 8; i++) {
        const int m = m0 + ty * 8 + i;
#pragma unroll
        for (int j = 0; j < 8; j += 4) {
            const int n = n0 + tx * 8 + j;
            float4 v;
            v.x = alpha * acc[i][j + 0];
            v.y = alpha * acc[i][j + 1];
            v.z = alpha * acc[i][j + 2];
            v.w = alpha * acc[i][j + 3];
            if (HAS_BIAS) {
                v.x += bias[n + 0];
                v.y += bias[n + 1];
                v.z += bias[n + 2];
                v.w += bias[n + 3];
            }
            *(float4*)&C[(size_t)m * N + n] = v;
        }
    }
}

// ---------------- in-place row softmax over N=8192 (row fits in smem) ----------------
__global__ void softmax_rows_kernel(float* __restrict__ S, int N)
{
    __shared__ float row[N_BANK];
    __shared__ float red[32];
    const int t = threadIdx.x;
    float* Sr = S + (size_t)blockIdx.x * N;

    float mx = -3.4e38f;
    for (int i = t; i < N; i += 256) {
        float v = Sr[i];
        row[i] = v;
        mx = fmaxf(mx, v);
    }
#pragma unroll
    for (int o = 16; o > 0; o >>= 1) mx = fmaxf(mx, __shfl_xor_sync(0xffffffffu, mx, o));
    if ((t & 31) == 0) red[t >> 5] = mx;
    __syncthreads();
    if (t == 0) {
        float m = red[0];
        for (int w = 1; w < 8; w++) m = fmaxf(m, red[w]);
        red[0] = m;
    }
    __syncthreads();
    mx = red[0];
    __syncthreads();

    float s = 0.f;
    for (int i = t; i < N; i += 256) {
        float e = __expf(row[i] - mx);
        row[i] = e;
        s += e;
    }
#pragma unroll
    for (int o = 16; o > 0; o >>= 1) s += __shfl_xor_sync(0xffffffffu, s, o);
    if ((t & 31) == 0) red[t >> 5] = s;
    __syncthreads();
    if (t == 0) {
        float m = 0.f;
        for (int w = 0; w < 8; w++) m += red[w];
        red[0] = m;
    }
    __syncthreads();
    const float inv = 1.f / red[0];
    for (int i = t; i < N; i += 256) Sr[i] = row[i] * inv;
}

// ---------------- cpair = f1*f2 -> LayerNorm -> PReLU ----------------
__global__ void gate_ln_prelu_kernel(const float* __restrict__ f1, const float* __restrict__ f2,
                                     const float* __restrict__ lnw, const float* __restrict__ lnb,
                                     const float* __restrict__ pa, float* __restrict__ x)
{
    const int t = threadIdx.x;
    const size_t base = (size_t)blockIdx.x * LATENT;
    __shared__ float redA[32];
    __shared__ float redB[32];

    float c[4];
    float sum = 0.f, ss = 0.f;
#pragma unroll
    for (int j = 0; j < 4; j++) {
        const int col = t + j * 256;
        float v = f1[base + col] * f2[base + col];
        c[j] = v;
        sum += v;
        ss += v * v;
    }
#pragma unroll
    for (int o = 16; o > 0; o >>= 1) {
        sum += __shfl_xor_sync(0xffffffffu, sum, o);
        ss  += __shfl_xor_sync(0xffffffffu, ss,  o);
    }
    if ((t & 31) == 0) { redA[t >> 5] = sum; redB[t >> 5] = ss; }
    __syncthreads();
    if (t == 0) {
        float a = 0.f, b = 0.f;
        for (int w = 0; w < 8; w++) { a += redA[w]; b += redB[w]; }
        redA[0] = a; redB[0] = b;
    }
    __syncthreads();
    const float mu   = redA[0] * (1.f / LATENT);
    const float var  = redB[0] * (1.f / LATENT) - mu * mu;
    const float rstd = rsqrtf(var + 1e-5f);
    const float a    = pa[0];
#pragma unroll
    for (int j = 0; j < 4; j++) {
        const int col = t + j * 256;
        float v = (c[j] - mu) * rstd * lnw[col] + lnb[col];
        x[base + col] = v >= 0.f ? v : a * v;
    }
}

// ---------------- launch ----------------
extern "C" void kernel_launch(void* const* d_in, const int* in_sizes, int n_in,
                              void* d_out, int out_size)
{
    const float* feat = (const float*)d_in[0];
    const float* bank = (const float*)d_in[1];
    const float* Wc1 = (const float*)d_in[2];  const float* bc1 = (const float*)d_in[3];
    const float* Wc2 = (const float*)d_in[4];  const float* bc2 = (const float*)d_in[5];
    const float* Wc3 = (const float*)d_in[6];  const float* bc3 = (const float*)d_in[7];
    const float* Wd1 = (const float*)d_in[8];  const float* bd1 = (const float*)d_in[9];
    const float* Wd2 = (const float*)d_in[10]; const float* bd2 = (const float*)d_in[11];
    const float* Wd3 = (const float*)d_in[12]; const float* bd3 = (const float*)d_in[13];
    const float* lnw = (const float*)d_in[14]; const float* lnb = (const float*)d_in[15];
    const float* pa  = (const float*)d_in[16];
    const float* Wffn = (const float*)d_in[17]; const float* bffn = (const float*)d_in[18];
    float* out = (float*)d_out;

    float *q1, *q2, *k1, *v1, *k2, *v2, *S, *f1, *f2, *x;
    cudaGetSymbolAddress((void**)&q1, g_q1);
    cudaGetSymbolAddress((void**)&q2, g_q2);
    cudaGetSymbolAddress((void**)&k1, g_k1);
    cudaGetSymbolAddress((void**)&v1, g_v1);
    cudaGetSymbolAddress((void**)&k2, g_k2);
    cudaGetSymbolAddress((void**)&v2, g_v2);
    cudaGetSymbolAddress((void**)&S,  g_S);
    cudaGetSymbolAddress((void**)&f1, g_f1);
    cudaGetSymbolAddress((void**)&f2, g_f2);
    cudaGetSymbolAddress((void**)&x,  g_x);

    const dim3 blk(256);
    const float scale = 1.0f / 32.0f;  // 1/sqrt(1024)

    // projections (NT, with bias)
    sgemm_kernel<true, true><<<dim3(LATENT / 128, N_ROIS / 128), blk>>>(feat, Wc1, bc1, q1, N_ROIS, LATENT, QDIM, 1.f);
    sgemm_kernel<true, true><<<dim3(LATENT / 128, N_ROIS / 128), blk>>>(feat, Wd1, bd1, q2, N_ROIS, LATENT, QDIM, 1.f);
    sgemm_kernel<true, true><<<dim3(LATENT / 128, N_BANK / 128), blk>>>(bank, Wc2, bc2, k1, N_BANK, LATENT, DIM_IN, 1.f);
    sgemm_kernel<true, true><<<dim3(LATENT / 128, N_BANK / 128), blk>>>(bank, Wc3, bc3, v1, N_BANK, LATENT, DIM_IN, 1.f);
    sgemm_kernel<true, true><<<dim3(LATENT / 128, N_BANK / 128), blk>>>(bank, Wd2, bd2, k2, N_BANK, LATENT, DIM_IN, 1.f);
    sgemm_kernel<true, true><<<dim3(LATENT / 128, N_BANK / 128), blk>>>(bank, Wd3, bd3, v2, N_BANK, LATENT, DIM_IN, 1.f);

    // branch 1 attention
    sgemm_kernel<true, false><<<dim3(N_BANK / 128, N_ROIS / 128), blk>>>(q1, k1, nullptr, S, N_ROIS, N_BANK, LATENT, scale);
    softmax_rows_kernel<<<N_ROIS, blk>>>(S, N_BANK);
    sgemm_kernel<false, false><<<dim3(LATENT / 128, N_ROIS / 128), blk>>>(S, v1, nullptr, f1, N_ROIS, LATENT, N_BANK, 1.f);

    // branch 2 attention (reuses S)
    sgemm_kernel<true, false><<<dim3(N_BANK / 128, N_ROIS / 128), blk>>>(q2, k2, nullptr, S, N_ROIS, N_BANK, LATENT, scale);
    softmax_rows_kernel<<<N_ROIS, blk>>>(S, N_BANK);
    sgemm_kernel<false, false><<<dim3(LATENT / 128, N_ROIS / 128), blk>>>(S, v2, nullptr, f2, N_ROIS, LATENT, N_BANK, 1.f);

    // gate + layernorm + prelu
    gate_ln_prelu_kernel<<<N_ROIS, blk>>>(f1, f2, lnw, lnb, pa, x);

    // FFN (NT, with bias) -> output
    sgemm_kernel<true, true><<<dim3(DIM_IN / 128, N_ROIS / 128), blk>>>(x, Wffn, bffn, out, N_ROIS, DIM_IN, LATENT, 1.f);
}

// round 3
// speedup vs baseline: 1.6134x; 1.6134x over previous
#include <cuda_runtime.h>
#include <cuda_bf16.h>
#include <stdint.h>
#include <math.h>

#define N_ROIS 4096
#define N_BANK 8192
#define DIM_IN 2048
#define QDIM   2048
#define LATENT 1024

// ---------------- scratch ----------------
__device__ float g_q1[N_ROIS * LATENT];
__device__ float g_q2[N_ROIS * LATENT];
__device__ float g_k1[N_BANK * LATENT];
__device__ float g_v1[N_BANK * LATENT];
__device__ float g_k2[N_BANK * LATENT];
__device__ float g_v2[N_BANK * LATENT];
__device__ float g_S [(size_t)N_ROIS * N_BANK];
__device__ float g_f1[N_ROIS * LATENT];
__device__ float g_f2[N_ROIS * LATENT];
__device__ float g_x [N_ROIS * LATENT];

// ---------------- helpers ----------------
__device__ __forceinline__ void split2(float x, float y, uint32_t& h, uint32_t& l) {
    __nv_bfloat162 hh, ll;
    hh.x = __float2bfloat16_rn(x);
    hh.y = __float2bfloat16_rn(y);
    ll.x = __float2bfloat16_rn(x - __bfloat162float(hh.x));
    ll.y = __float2bfloat16_rn(y - __bfloat162float(hh.y));
    h = *(uint32_t*)&hh;
    l = *(uint32_t*)&ll;
}

__device__ __forceinline__ void mma16816(float* c, const uint32_t* a, const uint32_t* b) {
    asm volatile(
        "mma.sync.aligned.m16n8k16.row.col.f32.bf16.bf16.f32 "
        "{%0,%1,%2,%3}, {%4,%5,%6,%7}, {%8,%9}, {%0,%1,%2,%3};"
        : "+f"(c[0]), "+f"(c[1]), "+f"(c[2]), "+f"(c[3])
        : "r"(a[0]), "r"(a[1]), "r"(a[2]), "r"(a[3]), "r"(b[0]), "r"(b[1]));
}

// ---------------- bf16-split tensor GEMM: C = alpha*(A @ opB) (+bias) ----------------
// A: [M,K] row-major fp32.
// TRANSB=true : B [N,K] row-major (NT).  TRANSB=false: B [K,N] row-major (NN).
// 128x128 tile, BK=32. smem tiles stored [row][32 bf16 + 8 pad] (80B stride).
static constexpr int BM = 128, BN = 128, BK = 32;
static constexpr int ROWB = 80;            // bytes per smem row
static constexpr int TILEB = 128 * ROWB;   // 10240 bytes per tile

template <bool TRANSB, bool HAS_BIAS>
__global__ void __launch_bounds__(256)
mma_gemm(const float* __restrict__ A, const float* __restrict__ B,
         const float* __restrict__ bias, float* __restrict__ C,
         int M, int N, int K, float alpha)
{
    __shared__ __align__(16) char smem[4 * TILEB];  // Ah, Al, Bh, Bl
    char* sAh = smem;
    char* sAl = smem + TILEB;
    char* sBh = smem + 2 * TILEB;
    char* sBl = smem + 3 * TILEB;

    const int t    = threadIdx.x;
    const int lane = t & 31;
    const int wid  = t >> 5;
    const int wm   = wid & 1;          // 2 warps in m
    const int wn   = wid >> 1;         // 4 warps in n
    const int g    = lane >> 2;        // group id 0..7
    const int tq   = lane & 3;         // thread-in-group
    const int m0   = blockIdx.y * BM;
    const int n0   = blockIdx.x * BN;

    float acc[4][4][4];
#pragma unroll
    for (int i = 0; i < 4; i++)
#pragma unroll
        for (int j = 0; j < 4; j++)
#pragma unroll
            for (int r = 0; r < 4; r++) acc[i][j][r] = 0.f;

    const int niter = K / BK;
    for (int it = 0; it < niter; it++) {
        const int k0 = it * BK;

        // ---- A tile: 128 rows x 32 floats -> split hi/lo bf16
#pragma unroll
        for (int p = 0; p < 4; p++) {
            const int idx = p * 256 + t;
            const int row = idx >> 3;
            const int c0  = (idx & 7) * 4;
            float4 v = *(const float4*)(A + (size_t)(m0 + row) * K + k0 + c0);
            uint32_t h01, l01, h23, l23;
            split2(v.x, v.y, h01, l01);
            split2(v.z, v.w, h23, l23);
            const int off = row * ROWB + c0 * 2;
            *(uint32_t*)(sAh + off)     = h01;
            *(uint32_t*)(sAh + off + 4) = h23;
            *(uint32_t*)(sAl + off)     = l01;
            *(uint32_t*)(sAl + off + 4) = l23;
        }
        // ---- B tile -> smem rows indexed by n (128), cols by k (32)
        if (TRANSB) {
#pragma unroll
            for (int p = 0; p < 4; p++) {
                const int idx = p * 256 + t;
                const int row = idx >> 3;
                const int c0  = (idx & 7) * 4;
                float4 v = *(const float4*)(B + (size_t)(n0 + row) * K + k0 + c0);
                uint32_t h01, l01, h23, l23;
                split2(v.x, v.y, h01, l01);
                split2(v.z, v.w, h23, l23);
                const int off = row * ROWB + c0 * 2;
                *(uint32_t*)(sBh + off)     = h01;
                *(uint32_t*)(sBh + off + 4) = h23;
                *(uint32_t*)(sBl + off)     = l01;
                *(uint32_t*)(sBl + off + 4) = l23;
            }
        } else {
#pragma unroll
            for (int p = 0; p < 4; p++) {
                const int idx = p * 256 + t;
                const int kk  = idx >> 5;
                const int nn  = (idx & 31) * 4;
                float4 v = *(const float4*)(B + (size_t)(k0 + kk) * N + n0 + nn);
                float vv[4] = {v.x, v.y, v.z, v.w};
#pragma unroll
                for (int j = 0; j < 4; j++) {
                    const int jj = (j + lane) & 3;   // stagger to limit write conflicts
                    __nv_bfloat16 h = __float2bfloat16_rn(vv[jj]);
                    __nv_bfloat16 l = __float2bfloat16_rn(vv[jj] - __bfloat162float(h));
                    const int off = (nn + jj) * ROWB + kk * 2;
                    *(__nv_bfloat16*)(sBh + off) = h;
                    *(__nv_bfloat16*)(sBl + off) = l;
                }
            }
        }
        __syncthreads();

        // ---- 2 ksteps of m16n8k16; 3 split products each
#pragma unroll
        for (int ks = 0; ks < 2; ks++) {
            const int cb = ks * 32 + tq * 4;  // byte offset of k-low within row
            uint32_t Ah[4][4], X[4][4], Bf[4][2];
#pragma unroll
            for (int i = 0; i < 4; i++) {
                const int r0 = (wm * 64 + i * 16 + g) * ROWB + cb;
                Ah[i][0] = *(const uint32_t*)(sAh + r0);
                Ah[i][1] = *(const uint32_t*)(sAh + r0 + 8 * ROWB);
                Ah[i][2] = *(const uint32_t*)(sAh + r0 + 16);
                Ah[i][3] = *(const uint32_t*)(sAh + r0 + 8 * ROWB + 16);
            }
#pragma unroll
            for (int j = 0; j < 4; j++) {
                const int r0 = (wn * 32 + j * 8 + g) * ROWB + cb;
                Bf[j][0] = *(const uint32_t*)(sBh + r0);
                Bf[j][1] = *(const uint32_t*)(sBh + r0 + 16);
            }
            // Ah * Bh
#pragma unroll
            for (int i = 0; i < 4; i++)
#pragma unroll
                for (int j = 0; j < 4; j++) mma16816(acc[i][j], Ah[i], Bf[j]);
            // Al * Bh
#pragma unroll
            for (int i = 0; i < 4; i++) {
                const int r0 = (wm * 64 + i * 16 + g) * ROWB + cb;
                X[i][0] = *(const uint32_t*)(sAl + r0);
                X[i][1] = *(const uint32_t*)(sAl + r0 + 8 * ROWB);
                X[i][2] = *(const uint32_t*)(sAl + r0 + 16);
                X[i][3] = *(const uint32_t*)(sAl + r0 + 8 * ROWB + 16);
            }
#pragma unroll
            for (int i = 0; i < 4; i++)
#pragma unroll
                for (int j = 0; j < 4; j++) mma16816(acc[i][j], X[i], Bf[j]);
            // Ah * Bl
#pragma unroll
            for (int j = 0; j < 4; j++) {
                const int r0 = (wn * 32 + j * 8 + g) * ROWB + cb;
                Bf[j][0] = *(const uint32_t*)(sBl + r0);
                Bf[j][1] = *(const uint32_t*)(sBl + r0 + 16);
            }
#pragma unroll
            for (int i = 0; i < 4; i++)
#pragma unroll
                for (int j = 0; j < 4; j++) mma16816(acc[i][j], Ah[i], Bf[j]);
        }
        __syncthreads();
    }

    // ---- epilogue: alpha, bias, direct float2 stores
#pragma unroll
    for (int i = 0; i < 4; i++) {
        const int mrow = m0 + wm * 64 + i * 16 + g;
#pragma unroll
        for (int j = 0; j < 4; j++) {
            const int ncol = n0 + wn * 32 + j * 8 + tq * 2;
            float2 v0, v1;
            v0.x = alpha * acc[i][j][0];
            v0.y = alpha * acc[i][j][1];
            v1.x = alpha * acc[i][j][2];
            v1.y = alpha * acc[i][j][3];
            if (HAS_BIAS) {
                const float b0 = bias[ncol], b1 = bias[ncol + 1];
                v0.x += b0; v0.y += b1;
                v1.x += b0; v1.y += b1;
            }
            *(float2*)(C + (size_t)mrow * N + ncol)       = v0;
            *(float2*)(C + (size_t)(mrow + 8) * N + ncol) = v1;
        }
    }
}

// ---------------- in-place row softmax over N=8192 ----------------
__global__ void softmax_rows_kernel(float* __restrict__ S, int N)
{
    __shared__ float row[N_BANK];
    __shared__ float red[32];
    const int t = threadIdx.x;
    float* Sr = S + (size_t)blockIdx.x * N;

    float mx = -3.4e38f;
    for (int i = t; i < N; i += 256) {
        float v = Sr[i];
        row[i] = v;
        mx = fmaxf(mx, v);
    }
#pragma unroll
    for (int o = 16; o > 0; o >>= 1) mx = fmaxf(mx, __shfl_xor_sync(0xffffffffu, mx, o));
    if ((t & 31) == 0) red[t >> 5] = mx;
    __syncthreads();
    if (t == 0) {
        float m = red[0];
        for (int w = 1; w < 8; w++) m = fmaxf(m, red[w]);
        red[0] = m;
    }
    __syncthreads();
    mx = red[0];
    __syncthreads();

    float s = 0.f;
    for (int i = t; i < N; i += 256) {
        float e = __expf(row[i] - mx);
        row[i] = e;
        s += e;
    }
#pragma unroll
    for (int o = 16; o > 0; o >>= 1) s += __shfl_xor_sync(0xffffffffu, s, o);
    if ((t & 31) == 0) red[t >> 5] = s;
    __syncthreads();
    if (t == 0) {
        float m = 0.f;
        for (int w = 0; w < 8; w++) m += red[w];
        red[0] = m;
    }
    __syncthreads();
    const float inv = 1.f / red[0];
    for (int i = t; i < N; i += 256) Sr[i] = row[i] * inv;
}

// ---------------- cpair = f1*f2 -> LayerNorm -> PReLU ----------------
__global__ void gate_ln_prelu_kernel(const float* __restrict__ f1, const float* __restrict__ f2,
                                     const float* __restrict__ lnw, const float* __restrict__ lnb,
                                     const float* __restrict__ pa, float* __restrict__ x)
{
    const int t = threadIdx.x;
    const size_t base = (size_t)blockIdx.x * LATENT;
    __shared__ float redA[32];
    __shared__ float redB[32];

    float c[4];
    float sum = 0.f, ss = 0.f;
#pragma unroll
    for (int j = 0; j < 4; j++) {
        const int col = t + j * 256;
        float v = f1[base + col] * f2[base + col];
        c[j] = v;
        sum += v;
        ss += v * v;
    }
#pragma unroll
    for (int o = 16; o > 0; o >>= 1) {
        sum += __shfl_xor_sync(0xffffffffu, sum, o);
        ss  += __shfl_xor_sync(0xffffffffu, ss,  o);
    }
    if ((t & 31) == 0) { redA[t >> 5] = sum; redB[t >> 5] = ss; }
    __syncthreads();
    if (t == 0) {
        float a = 0.f, b = 0.f;
        for (int w = 0; w < 8; w++) { a += redA[w]; b += redB[w]; }
        redA[0] = a; redB[0] = b;
    }
    __syncthreads();
    const float mu   = redA[0] * (1.f / LATENT);
    const float var  = redB[0] * (1.f / LATENT) - mu * mu;
    const float rstd = rsqrtf(var + 1e-5f);
    const float a    = pa[0];
#pragma unroll
    for (int j = 0; j < 4; j++) {
        const int col = t + j * 256;
        float v = (c[j] - mu) * rstd * lnw[col] + lnb[col];
        x[base + col] = v >= 0.f ? v : a * v;
    }
}

// ---------------- launch ----------------
extern "C" void kernel_launch(void* const* d_in, const int* in_sizes, int n_in,
                              void* d_out, int out_size)
{
    const float* feat = (const float*)d_in[0];
    const float* bank = (const float*)d_in[1];
    const float* Wc1 = (const float*)d_in[2];  const float* bc1 = (const float*)d_in[3];
    const float* Wc2 = (const float*)d_in[4];  const float* bc2 = (const float*)d_in[5];
    const float* Wc3 = (const float*)d_in[6];  const float* bc3 = (const float*)d_in[7];
    const float* Wd1 = (const float*)d_in[8];  const float* bd1 = (const float*)d_in[9];
    const float* Wd2 = (const float*)d_in[10]; const float* bd2 = (const float*)d_in[11];
    const float* Wd3 = (const float*)d_in[12]; const float* bd3 = (const float*)d_in[13];
    const float* lnw = (const float*)d_in[14]; const float* lnb = (const float*)d_in[15];
    const float* pa  = (const float*)d_in[16];
    const float* Wffn = (const float*)d_in[17]; const float* bffn = (const float*)d_in[18];
    float* out = (float*)d_out;

    float *q1, *q2, *k1, *v1, *k2, *v2, *S, *f1, *f2, *x;
    cudaGetSymbolAddress((void**)&q1, g_q1);
    cudaGetSymbolAddress((void**)&q2, g_q2);
    cudaGetSymbolAddress((void**)&k1, g_k1);
    cudaGetSymbolAddress((void**)&v1, g_v1);
    cudaGetSymbolAddress((void**)&k2, g_k2);
    cudaGetSymbolAddress((void**)&v2, g_v2);
    cudaGetSymbolAddress((void**)&S,  g_S);
    cudaGetSymbolAddress((void**)&f1, g_f1);
    cudaGetSymbolAddress((void**)&f2, g_f2);
    cudaGetSymbolAddress((void**)&x,  g_x);

    const dim3 blk(256);
    const float scale = 1.0f / 32.0f;  // 1/sqrt(1024)

    // projections (NT, with bias)
    mma_gemm<true, true><<<dim3(LATENT/128, N_ROIS/128), blk>>>(feat, Wc1, bc1, q1, N_ROIS, LATENT, QDIM, 1.f);
    mma_gemm<true, true><<<dim3(LATENT/128, N_ROIS/128), blk>>>(feat, Wd1, bd1, q2, N_ROIS, LATENT, QDIM, 1.f);
    mma_gemm<true, true><<<dim3(LATENT/128, N_BANK/128), blk>>>(bank, Wc2, bc2, k1, N_BANK, LATENT, DIM_IN, 1.f);
    mma_gemm<true, true><<<dim3(LATENT/128, N_BANK/128), blk>>>(bank, Wc3, bc3, v1, N_BANK, LATENT, DIM_IN, 1.f);
    mma_gemm<true, true><<<dim3(LATENT/128, N_BANK/128), blk>>>(bank, Wd2, bd2, k2, N_BANK, LATENT, DIM_IN, 1.f);
    mma_gemm<true, true><<<dim3(LATENT/128, N_BANK/128), blk>>>(bank, Wd3, bd3, v2, N_BANK, LATENT, DIM_IN, 1.f);

    // branch 1 attention
    mma_gemm<true, false><<<dim3(N_BANK/128, N_ROIS/128), blk>>>(q1, k1, nullptr, S, N_ROIS, N_BANK, LATENT, scale);
    softmax_rows_kernel<<<N_ROIS, blk>>>(S, N_BANK);
    mma_gemm<false, false><<<dim3(LATENT/128, N_ROIS/128), blk>>>(S, v1, nullptr, f1, N_ROIS, LATENT, N_BANK, 1.f);

    // branch 2 attention (reuses S)
    mma_gemm<true, false><<<dim3(N_BANK/128, N_ROIS/128), blk>>>(q2, k2, nullptr, S, N_ROIS, N_BANK, LATENT, scale);
    softmax_rows_kernel<<<N_ROIS, blk>>>(S, N_BANK);
    mma_gemm<false, false><<<dim3(LATENT/128, N_ROIS/128), blk>>>(S, v2, nullptr, f2, N_ROIS, LATENT, N_BANK, 1.f);

    // gate + layernorm + prelu
    gate_ln_prelu_kernel<<<N_ROIS, blk>>>(f1, f2, lnw, lnb, pa, x);

    // FFN (NT, with bias) -> output
    mma_gemm<true, true><<<dim3(DIM_IN/128, N_ROIS/128), blk>>>(x, Wffn, bffn, out, N_ROIS, DIM_IN, LATENT, 1.f);
}

// round 5
// speedup vs baseline: 2.0493x; 1.2701x over previous
#include <cuda_runtime.h>
#include <cuda_bf16.h>
#include <stdint.h>
#include <math.h>

#define N_ROIS 4096
#define N_BANK 8192
#define DIM_IN 2048
#define QDIM   2048
#define LATENT 1024

// ---------------- scratch ----------------
__device__ float g_q1[N_ROIS * LATENT];
__device__ float g_q2[N_ROIS * LATENT];
__device__ float g_k1[N_BANK * LATENT];
__device__ float g_v1[N_BANK * LATENT];
__device__ float g_k2[N_BANK * LATENT];
__device__ float g_v2[N_BANK * LATENT];
__device__ float g_S [(size_t)N_ROIS * N_BANK];
__device__ float g_f1[N_ROIS * LATENT];
__device__ float g_f2[N_ROIS * LATENT];
__device__ float g_x [N_ROIS * LATENT];

// ---------------- helpers ----------------
__device__ __forceinline__ void split2(float x, float y, uint32_t& h, uint32_t& l) {
    __nv_bfloat162 hh, ll;
    hh.x = __float2bfloat16_rn(x);
    hh.y = __float2bfloat16_rn(y);
    ll.x = __float2bfloat16_rn(x - __bfloat162float(hh.x));
    ll.y = __float2bfloat16_rn(y - __bfloat162float(hh.y));
    h = *(uint32_t*)&hh;
    l = *(uint32_t*)&ll;
}

__device__ __forceinline__ void mma16816(float* c, const uint32_t* a, const uint32_t* b) {
    asm volatile(
        "mma.sync.aligned.m16n8k16.row.col.f32.bf16.bf16.f32 "
        "{%0,%1,%2,%3}, {%4,%5,%6,%7}, {%8,%9}, {%0,%1,%2,%3};"
        : "+f"(c[0]), "+f"(c[1]), "+f"(c[2]), "+f"(c[3])
        : "r"(a[0]), "r"(a[1]), "r"(a[2]), "r"(a[3]), "r"(b[0]), "r"(b[1]));
}

// ---------------- bf16-split tensor GEMM, 2-stage pipelined ----------------
// C = alpha*(A @ opB) (+bias).  A: [M,K] row-major fp32.
// TRANSB=true : B [N,K] row-major (NT).  TRANSB=false: B [K,N] row-major (NN).
// 128x128 tile, BK=32. smem rows: 32 bf16 + 8 pad = 80B stride. Two stages.
static constexpr int BM = 128, BN = 128, BK = 32;
static constexpr int ROWB = 80;
static constexpr int TILEB = 128 * ROWB;          // 10240
static constexpr int STAGEB = 4 * TILEB;          // Ah,Al,Bh,Bl = 40960
static constexpr int SMEM_TOTAL = 2 * STAGEB;     // 81920

template <bool TRANSB, bool HAS_BIAS>
__global__ void __launch_bounds__(256)
mma_gemm(const float* __restrict__ A, const float* __restrict__ B,
         const float* __restrict__ bias, float* __restrict__ C,
         int M, int N, int K, float alpha)
{
    extern __shared__ __align__(16) char smem[];

    const int t    = threadIdx.x;
    const int lane = t & 31;
    const int wid  = t >> 5;
    const int wm   = wid & 1;
    const int wn   = wid >> 1;
    const int g    = lane >> 2;
    const int tq   = lane & 3;
    const int m0   = blockIdx.y * BM;
    const int n0   = blockIdx.x * BN;

    // per-thread load geometry
    const int ar = t >> 3;            // + p*32 : row
    const int ac = (t & 7) * 4;       // float col
    const int bkk = t >> 5;           // + p*8 : k row (NN)
    const int bnn = (t & 31) * 4;     // n col (NN)

    float4 aR[4], bR[4];

    auto load_tile = [&](int k0) {
#pragma unroll
        for (int p = 0; p < 4; p++)
            aR[p] = *(const float4*)(A + (size_t)(m0 + p * 32 + ar) * K + k0 + ac);
        if (TRANSB) {
#pragma unroll
            for (int p = 0; p < 4; p++)
                bR[p] = *(const float4*)(B + (size_t)(n0 + p * 32 + ar) * K + k0 + ac);
        } else {
#pragma unroll
            for (int p = 0; p < 4; p++)
                bR[p] = *(const float4*)(B + (size_t)(k0 + p * 8 + bkk) * N + n0 + bnn);
        }
    };

    auto store_tile = [&](int stage) {
        char* sAh = smem + stage * STAGEB;
        char* sAl = sAh + TILEB;
        char* sBh = sAh + 2 * TILEB;
        char* sBl = sAh + 3 * TILEB;
#pragma unroll
        for (int p = 0; p < 4; p++) {
            uint32_t h01, l01, h23, l23;
            split2(aR[p].x, aR[p].y, h01, l01);
            split2(aR[p].z, aR[p].w, h23, l23);
            const int off = (p * 32 + ar) * ROWB + ac * 2;
            *(uint32_t*)(sAh + off)     = h01;
            *(uint32_t*)(sAh + off + 4) = h23;
            *(uint32_t*)(sAl + off)     = l01;
            *(uint32_t*)(sAl + off + 4) = l23;
        }
        if (TRANSB) {
#pragma unroll
            for (int p = 0; p < 4; p++) {
                uint32_t h01, l01, h23, l23;
                split2(bR[p].x, bR[p].y, h01, l01);
                split2(bR[p].z, bR[p].w, h23, l23);
                const int off = (p * 32 + ar) * ROWB + ac * 2;
                *(uint32_t*)(sBh + off)     = h01;
                *(uint32_t*)(sBh + off + 4) = h23;
                *(uint32_t*)(sBl + off)     = l01;
                *(uint32_t*)(sBl + off + 4) = l23;
            }
        } else {
#pragma unroll
            for (int p = 0; p < 4; p++) {
                float vv[4] = {bR[p].x, bR[p].y, bR[p].z, bR[p].w};
                const int kk = p * 8 + bkk;
#pragma unroll
                for (int j = 0; j < 4; j++) {
                    const int jj = (j + lane) & 3;   // stagger writes
                    __nv_bfloat16 h = __float2bfloat16_rn(vv[jj]);
                    __nv_bfloat16 l = __float2bfloat16_rn(vv[jj] - __bfloat162float(h));
                    const int off = (bnn + jj) * ROWB + kk * 2;
                    *(__nv_bfloat16*)(sBh + off) = h;
                    *(__nv_bfloat16*)(sBl + off) = l;
                }
            }
        }
    };

    float acc[4][4][4];
#pragma unroll
    for (int i = 0; i < 4; i++)
#pragma unroll
        for (int j = 0; j < 4; j++)
#pragma unroll
            for (int r = 0; r < 4; r++) acc[i][j][r] = 0.f;

    const int niter = K / BK;

    // prologue: fill stage 0
    load_tile(0);
    store_tile(0);
    __syncthreads();

    for (int it = 0; it < niter; it++) {
        const int cur = it & 1;

        // 1) issue next tile's global loads early (latency hidden by MMAs below)
        if (it + 1 < niter) load_tile((it + 1) * BK);

        // 2) MMAs on current stage
        {
            char* sAh = smem + cur * STAGEB;
            char* sAl = sAh + TILEB;
            char* sBh = sAh + 2 * TILEB;
            char* sBl = sAh + 3 * TILEB;
#pragma unroll
            for (int ks = 0; ks < 2; ks++) {
                const int cb = ks * 32 + tq * 4;
                uint32_t Ah[4][4], X[4][4], Bf[4][2];
#pragma unroll
                for (int i = 0; i < 4; i++) {
                    const int r0 = (wm * 64 + i * 16 + g) * ROWB + cb;
                    Ah[i][0] = *(const uint32_t*)(sAh + r0);
                    Ah[i][1] = *(const uint32_t*)(sAh + r0 + 8 * ROWB);
                    Ah[i][2] = *(const uint32_t*)(sAh + r0 + 16);
                    Ah[i][3] = *(const uint32_t*)(sAh + r0 + 8 * ROWB + 16);
                }
#pragma unroll
                for (int j = 0; j < 4; j++) {
                    const int r0 = (wn * 32 + j * 8 + g) * ROWB + cb;
                    Bf[j][0] = *(const uint32_t*)(sBh + r0);
                    Bf[j][1] = *(const uint32_t*)(sBh + r0 + 16);
                }
#pragma unroll
                for (int i = 0; i < 4; i++)
#pragma unroll
                    for (int j = 0; j < 4; j++) mma16816(acc[i][j], Ah[i], Bf[j]);
#pragma unroll
                for (int i = 0; i < 4; i++) {
                    const int r0 = (wm * 64 + i * 16 + g) * ROWB + cb;
                    X[i][0] = *(const uint32_t*)(sAl + r0);
                    X[i][1] = *(const uint32_t*)(sAl + r0 + 8 * ROWB);
                    X[i][2] = *(const uint32_t*)(sAl + r0 + 16);
                    X[i][3] = *(const uint32_t*)(sAl + r0 + 8 * ROWB + 16);
                }
#pragma unroll
                for (int i = 0; i < 4; i++)
#pragma unroll
                    for (int j = 0; j < 4; j++) mma16816(acc[i][j], X[i], Bf[j]);
#pragma unroll
                for (int j = 0; j < 4; j++) {
                    const int r0 = (wn * 32 + j * 8 + g) * ROWB + cb;
                    Bf[j][0] = *(const uint32_t*)(sBl + r0);
                    Bf[j][1] = *(const uint32_t*)(sBl + r0 + 16);
                }
#pragma unroll
                for (int i = 0; i < 4; i++)
#pragma unroll
                    for (int j = 0; j < 4; j++) mma16816(acc[i][j], Ah[i], Bf[j]);
            }
        }

        // 3) convert+store next tile into the other stage
        if (it + 1 < niter) store_tile(cur ^ 1);
        __syncthreads();
    }

    // ---- epilogue
#pragma unroll
    for (int i = 0; i < 4; i++) {
        const int mrow = m0 + wm * 64 + i * 16 + g;
#pragma unroll
        for (int j = 0; j < 4; j++) {
            const int ncol = n0 + wn * 32 + j * 8 + tq * 2;
            float2 v0, v1;
            v0.x = alpha * acc[i][j][0];
            v0.y = alpha * acc[i][j][1];
            v1.x = alpha * acc[i][j][2];
            v1.y = alpha * acc[i][j][3];
            if (HAS_BIAS) {
                const float b0 = bias[ncol], b1 = bias[ncol + 1];
                v0.x += b0; v0.y += b1;
                v1.x += b0; v1.y += b1;
            }
            *(float2*)(C + (size_t)mrow * N + ncol)       = v0;
            *(float2*)(C + (size_t)(mrow + 8) * N + ncol) = v1;
        }
    }
}

// ---------------- in-place row softmax over N=8192 ----------------
__global__ void softmax_rows_kernel(float* __restrict__ S, int N)
{
    __shared__ float row[N_BANK];
    __shared__ float red[32];
    const int t = threadIdx.x;
    float* Sr = S + (size_t)blockIdx.x * N;

    float mx = -3.4e38f;
    for (int i = t; i < N; i += 256) {
        float v = Sr[i];
        row[i] = v;
        mx = fmaxf(mx, v);
    }
#pragma unroll
    for (int o = 16; o > 0; o >>= 1) mx = fmaxf(mx, __shfl_xor_sync(0xffffffffu, mx, o));
    if ((t & 31) == 0) red[t >> 5] = mx;
    __syncthreads();
    if (t == 0) {
        float m = red[0];
        for (int w = 1; w < 8; w++) m = fmaxf(m, red[w]);
        red[0] = m;
    }
    __syncthreads();
    mx = red[0];
    __syncthreads();

    float s = 0.f;
    for (int i = t; i < N; i += 256) {
        float e = __expf(row[i] - mx);
        row[i] = e;
        s += e;
    }
#pragma unroll
    for (int o = 16; o > 0; o >>= 1) s += __shfl_xor_sync(0xffffffffu, s, o);
    if ((t & 31) == 0) red[t >> 5] = s;
    __syncthreads();
    if (t == 0) {
        float m = 0.f;
        for (int w = 0; w < 8; w++) m += red[w];
        red[0] = m;
    }
    __syncthreads();
    const float inv = 1.f / red[0];
    for (int i = t; i < N; i += 256) Sr[i] = row[i] * inv;
}

// ---------------- cpair = f1*f2 -> LayerNorm -> PReLU ----------------
__global__ void gate_ln_prelu_kernel(const float* __restrict__ f1, const float* __restrict__ f2,
                                     const float* __restrict__ lnw, const float* __restrict__ lnb,
                                     const float* __restrict__ pa, float* __restrict__ x)
{
    const int t = threadIdx.x;
    const size_t base = (size_t)blockIdx.x * LATENT;
    __shared__ float redA[32];
    __shared__ float redB[32];

    float c[4];
    float sum = 0.f, ss = 0.f;
#pragma unroll
    for (int j = 0; j < 4; j++) {
        const int col = t + j * 256;
        float v = f1[base + col] * f2[base + col];
        c[j] = v;
        sum += v;
        ss += v * v;
    }
#pragma unroll
    for (int o = 16; o > 0; o >>= 1) {
        sum += __shfl_xor_sync(0xffffffffu, sum, o);
        ss  += __shfl_xor_sync(0xffffffffu, ss,  o);
    }
    if ((t & 31) == 0) { redA[t >> 5] = sum; redB[t >> 5] = ss; }
    __syncthreads();
    if (t == 0) {
        float a = 0.f, b = 0.f;
        for (int w = 0; w < 8; w++) { a += redA[w]; b += redB[w]; }
        redA[0] = a; redB[0] = b;
    }
    __syncthreads();
    const float mu   = redA[0] * (1.f / LATENT);
    const float var  = redB[0] * (1.f / LATENT) - mu * mu;
    const float rstd = rsqrtf(var + 1e-5f);
    const float a    = pa[0];
#pragma unroll
    for (int j = 0; j < 4; j++) {
        const int col = t + j * 256;
        float v = (c[j] - mu) * rstd * lnw[col] + lnb[col];
        x[base + col] = v >= 0.f ? v : a * v;
    }
}

// ---------------- launch ----------------
extern "C" void kernel_launch(void* const* d_in, const int* in_sizes, int n_in,
                              void* d_out, int out_size)
{
    const float* feat = (const float*)d_in[0];
    const float* bank = (const float*)d_in[1];
    const float* Wc1 = (const float*)d_in[2];  const float* bc1 = (const float*)d_in[3];
    const float* Wc2 = (const float*)d_in[4];  const float* bc2 = (const float*)d_in[5];
    const float* Wc3 = (const float*)d_in[6];  const float* bc3 = (const float*)d_in[7];
    const float* Wd1 = (const float*)d_in[8];  const float* bd1 = (const float*)d_in[9];
    const float* Wd2 = (const float*)d_in[10]; const float* bd2 = (const float*)d_in[11];
    const float* Wd3 = (const float*)d_in[12]; const float* bd3 = (const float*)d_in[13];
    const float* lnw = (const float*)d_in[14]; const float* lnb = (const float*)d_in[15];
    const float* pa  = (const float*)d_in[16];
    const float* Wffn = (const float*)d_in[17]; const float* bffn = (const float*)d_in[18];
    float* out = (float*)d_out;

    float *q1, *q2, *k1, *v1, *k2, *v2, *S, *f1, *f2, *x;
    cudaGetSymbolAddress((void**)&q1, g_q1);
    cudaGetSymbolAddress((void**)&q2, g_q2);
    cudaGetSymbolAddress((void**)&k1, g_k1);
    cudaGetSymbolAddress((void**)&v1, g_v1);
    cudaGetSymbolAddress((void**)&k2, g_k2);
    cudaGetSymbolAddress((void**)&v2, g_v2);
    cudaGetSymbolAddress((void**)&S,  g_S);
    cudaGetSymbolAddress((void**)&f1, g_f1);
    cudaGetSymbolAddress((void**)&f2, g_f2);
    cudaGetSymbolAddress((void**)&x,  g_x);

    cudaFuncSetAttribute(mma_gemm<true, true>,   cudaFuncAttributeMaxDynamicSharedMemorySize, SMEM_TOTAL);
    cudaFuncSetAttribute(mma_gemm<true, false>,  cudaFuncAttributeMaxDynamicSharedMemorySize, SMEM_TOTAL);
    cudaFuncSetAttribute(mma_gemm<false, false>, cudaFuncAttributeMaxDynamicSharedMemorySize, SMEM_TOTAL);

    const dim3 blk(256);
    const float scale = 1.0f / 32.0f;  // 1/sqrt(1024)

    // projections (NT, with bias)
    mma_gemm<true, true><<<dim3(LATENT/128, N_ROIS/128), blk, SMEM_TOTAL>>>(feat, Wc1, bc1, q1, N_ROIS, LATENT, QDIM, 1.f);
    mma_gemm<true, true><<<dim3(LATENT/128, N_ROIS/128), blk, SMEM_TOTAL>>>(feat, Wd1, bd1, q2, N_ROIS, LATENT, QDIM, 1.f);
    mma_gemm<true, true><<<dim3(LATENT/128, N_BANK/128), blk, SMEM_TOTAL>>>(bank, Wc2, bc2, k1, N_BANK, LATENT, DIM_IN, 1.f);
    mma_gemm<true, true><<<dim3(LATENT/128, N_BANK/128), blk, SMEM_TOTAL>>>(bank, Wc3, bc3, v1, N_BANK, LATENT, DIM_IN, 1.f);
    mma_gemm<true, true><<<dim3(LATENT/128, N_BANK/128), blk, SMEM_TOTAL>>>(bank, Wd2, bd2, k2, N_BANK, LATENT, DIM_IN, 1.f);
    mma_gemm<true, true><<<dim3(LATENT/128, N_BANK/128), blk, SMEM_TOTAL>>>(bank, Wd3, bd3, v2, N_BANK, LATENT, DIM_IN, 1.f);

    // branch 1 attention
    mma_gemm<true, false><<<dim3(N_BANK/128, N_ROIS/128), blk, SMEM_TOTAL>>>(q1, k1, nullptr, S, N_ROIS, N_BANK, LATENT, scale);
    softmax_rows_kernel<<<N_ROIS, blk>>>(S, N_BANK);
    mma_gemm<false, false><<<dim3(LATENT/128, N_ROIS/128), blk, SMEM_TOTAL>>>(S, v1, nullptr, f1, N_ROIS, LATENT, N_BANK, 1.f);

    // branch 2 attention (reuses S)
    mma_gemm<true, false><<<dim3(N_BANK/128, N_ROIS/128), blk, SMEM_TOTAL>>>(q2, k2, nullptr, S, N_ROIS, N_BANK, LATENT, scale);
    softmax_rows_kernel<<<N_ROIS, blk>>>(S, N_BANK);
    mma_gemm<false, false><<<dim3(LATENT/128, N_ROIS/128), blk, SMEM_TOTAL>>>(S, v2, nullptr, f2, N_ROIS, LATENT, N_BANK, 1.f);

    // gate + layernorm + prelu
    gate_ln_prelu_kernel<<<N_ROIS, blk>>>(f1, f2, lnw, lnb, pa, x);

    // FFN (NT, with bias) -> output
    mma_gemm<true, true><<<dim3(DIM_IN/128, N_ROIS/128), blk, SMEM_TOTAL>>>(x, Wffn, bffn, out, N_ROIS, DIM_IN, LATENT, 1.f);
}

// round 6
// speedup vs baseline: 2.5982x; 1.2679x over previous
#include <cuda_runtime.h>
#include <cuda_bf16.h>
#include <stdint.h>
#include <math.h>

#define N_ROIS 4096
#define N_BANK 8192
#define DIM_IN 2048
#define QDIM   2048
#define LATENT 1024

typedef __nv_bfloat16 bf16;

// ---------------- scratch ----------------
__device__ bf16 g_feath[N_ROIS * QDIM],  g_featl[N_ROIS * QDIM];
__device__ bf16 g_bankh[N_BANK * DIM_IN], g_bankl[N_BANK * DIM_IN];
__device__ bf16 g_wc1h[LATENT * QDIM],   g_wc1l[LATENT * QDIM];
__device__ bf16 g_wc2h[LATENT * DIM_IN], g_wc2l[LATENT * DIM_IN];
__device__ bf16 g_wc3h[LATENT * DIM_IN], g_wc3l[LATENT * DIM_IN];
__device__ bf16 g_wd1h[LATENT * QDIM],   g_wd1l[LATENT * QDIM];
__device__ bf16 g_wd2h[LATENT * DIM_IN], g_wd2l[LATENT * DIM_IN];
__device__ bf16 g_wd3h[LATENT * DIM_IN], g_wd3l[LATENT * DIM_IN];
__device__ bf16 g_wfh[DIM_IN * LATENT],  g_wfl[DIM_IN * LATENT];
__device__ bf16 g_q1h[N_ROIS * LATENT],  g_q1l[N_ROIS * LATENT];
__device__ bf16 g_q2h[N_ROIS * LATENT],  g_q2l[N_ROIS * LATENT];
__device__ bf16 g_k1h[N_BANK * LATENT],  g_k1l[N_BANK * LATENT];
__device__ bf16 g_k2h[N_BANK * LATENT],  g_k2l[N_BANK * LATENT];
__device__ bf16 g_v1h[LATENT * N_BANK],  g_v1l[LATENT * N_BANK];   // v1T [latent, bank]
__device__ bf16 g_v2h[LATENT * N_BANK],  g_v2l[LATENT * N_BANK];
__device__ float g_S[(size_t)N_ROIS * N_BANK];
__device__ bf16 g_Ph[(size_t)N_ROIS * N_BANK], g_Pl[(size_t)N_ROIS * N_BANK];
__device__ float g_f1[N_ROIS * LATENT], g_f2[N_ROIS * LATENT];
__device__ bf16 g_xh[N_ROIS * LATENT],  g_xl[N_ROIS * LATENT];

// ---------------- helpers ----------------
__device__ __forceinline__ void mma16816(float* c, const uint32_t* a, const uint32_t* b) {
    asm volatile(
        "mma.sync.aligned.m16n8k16.row.col.f32.bf16.bf16.f32 "
        "{%0,%1,%2,%3}, {%4,%5,%6,%7}, {%8,%9}, {%0,%1,%2,%3};"
        : "+f"(c[0]), "+f"(c[1]), "+f"(c[2]), "+f"(c[3])
        : "r"(a[0]), "r"(a[1]), "r"(a[2]), "r"(a[3]), "r"(b[0]), "r"(b[1]));
}

__device__ __forceinline__ void cp16(uint32_t saddr, const void* gptr) {
    asm volatile("cp.async.cg.shared.global [%0], [%1], 16;" :: "r"(saddr), "l"(gptr));
}

// ---------------- fp32 -> (hi, lo) bf16 pre-split ----------------
__global__ void presplit_kernel(const float* __restrict__ s, bf16* __restrict__ h,
                                bf16* __restrict__ l, int n)
{
    int i = (blockIdx.x * 256 + threadIdx.x) * 4;
    if (i >= n) return;
    float4 v = *(const float4*)(s + i);
    __nv_bfloat162 h01, h23, l01, l23;
    h01.x = __float2bfloat16_rn(v.x); l01.x = __float2bfloat16_rn(v.x - __bfloat162float(h01.x));
    h01.y = __float2bfloat16_rn(v.y); l01.y = __float2bfloat16_rn(v.y - __bfloat162float(h01.y));
    h23.x = __float2bfloat16_rn(v.z); l23.x = __float2bfloat16_rn(v.z - __bfloat162float(h23.x));
    h23.y = __float2bfloat16_rn(v.w); l23.y = __float2bfloat16_rn(v.w - __bfloat162float(h23.y));
    *(__nv_bfloat162*)(h + i)     = h01;
    *(__nv_bfloat162*)(h + i + 2) = h23;
    *(__nv_bfloat162*)(l + i)     = l01;
    *(__nv_bfloat162*)(l + i + 2) = l23;
}

// ---------------- NT GEMM on pre-split bf16: C = alpha*(A @ B^T) (+bias) ----------------
// A: [M,K] (Ah,Al), B: [N,K] (Bh,Bl), both row-major bf16.
// BIAS_MODE: 0 none, 1 per-col (bias[n]), 2 per-row (bias[m]).
// OUT_SPLIT: write (Ch,Cl) bf16 pair instead of fp32 C.
static constexpr int BK = 32;
static constexpr int ROWB = 80;                 // 64B data + 16B pad
static constexpr int TILEB = 128 * ROWB;        // 10240
static constexpr int STAGEB = 4 * TILEB;        // Ah,Al,Bh,Bl = 40960
static constexpr int NSTAGES = 3;
static constexpr int SMEM_TOTAL = NSTAGES * STAGEB;   // 122880

template <int BIAS_MODE, bool OUT_SPLIT>
__global__ void __launch_bounds__(256)
gemm_bf(const bf16* __restrict__ Ah, const bf16* __restrict__ Al,
        const bf16* __restrict__ Bh, const bf16* __restrict__ Bl,
        const float* __restrict__ bias,
        float* __restrict__ C, bf16* __restrict__ Ch, bf16* __restrict__ Cl,
        int M, int N, int K, float alpha)
{
    extern __shared__ __align__(16) char smem[];
    const uint32_t sb = (uint32_t)__cvta_generic_to_shared(smem);

    const int t    = threadIdx.x;
    const int lane = t & 31;
    const int wid  = t >> 5;
    const int wm   = wid & 1;
    const int wn   = wid >> 1;
    const int g    = lane >> 2;
    const int tq   = lane & 3;
    const int m0   = blockIdx.y * 128;
    const int n0   = blockIdx.x * 128;

    const int niter = K / BK;

    // per-thread cp.async geometry: chunkid = p*256+t; row=chunkid>>2; 16B chunk (chunkid&3)
    auto issue_stage = [&](int s, int k0) {
        const uint32_t st = sb + s * STAGEB;
#pragma unroll
        for (int p = 0; p < 2; p++) {
            const int cid = p * 256 + t;
            const int row = cid >> 2;
            const int cq  = cid & 3;          // 16B chunk = 8 bf16
            const uint32_t so = st + row * ROWB + cq * 16;
            const size_t ga = (size_t)(m0 + row) * K + k0 + cq * 8;
            const size_t gb = (size_t)(n0 + row) * K + k0 + cq * 8;
            cp16(so,             Ah + ga);
            cp16(so + TILEB,     Al + ga);
            cp16(so + 2 * TILEB, Bh + gb);
            cp16(so + 3 * TILEB, Bl + gb);
        }
    };

    // prologue: stages 0..NSTAGES-2
#pragma unroll
    for (int s = 0; s < NSTAGES - 1; s++) {
        issue_stage(s, s * BK);
        asm volatile("cp.async.commit_group;");
    }

    float acc[4][4][4];
#pragma unroll
    for (int i = 0; i < 4; i++)
#pragma unroll
        for (int j = 0; j < 4; j++)
#pragma unroll
            for (int r = 0; r < 4; r++) acc[i][j][r] = 0.f;

    for (int it = 0; it < niter; it++) {
        asm volatile("cp.async.wait_group %0;" :: "n"(NSTAGES - 2));
        __syncthreads();

        const int cur = it % NSTAGES;
        char* sAh = smem + cur * STAGEB;
        char* sAl = sAh + TILEB;
        char* sBh = sAh + 2 * TILEB;
        char* sBl = sAh + 3 * TILEB;

#pragma unroll
        for (int ks = 0; ks < 2; ks++) {
            const int cb = ks * 32 + tq * 4;
            uint32_t Ahf[4][4], X[4][4], Bf[4][2];
#pragma unroll
            for (int i = 0; i < 4; i++) {
                const int r0 = (wm * 64 + i * 16 + g) * ROWB + cb;
                Ahf[i][0] = *(const uint32_t*)(sAh + r0);
                Ahf[i][1] = *(const uint32_t*)(sAh + r0 + 8 * ROWB);
                Ahf[i][2] = *(const uint32_t*)(sAh + r0 + 16);
                Ahf[i][3] = *(const uint32_t*)(sAh + r0 + 8 * ROWB + 16);
            }
#pragma unroll
            for (int j = 0; j < 4; j++) {
                const int r0 = (wn * 32 + j * 8 + g) * ROWB + cb;
                Bf[j][0] = *(const uint32_t*)(sBh + r0);
                Bf[j][1] = *(const uint32_t*)(sBh + r0 + 16);
            }
#pragma unroll
            for (int i = 0; i < 4; i++)
#pragma unroll
                for (int j = 0; j < 4; j++) mma16816(acc[i][j], Ahf[i], Bf[j]);
#pragma unroll
            for (int i = 0; i < 4; i++) {
                const int r0 = (wm * 64 + i * 16 + g) * ROWB + cb;
                X[i][0] = *(const uint32_t*)(sAl + r0);
                X[i][1] = *(const uint32_t*)(sAl + r0 + 8 * ROWB);
                X[i][2] = *(const uint32_t*)(sAl + r0 + 16);
                X[i][3] = *(const uint32_t*)(sAl + r0 + 8 * ROWB + 16);
            }
#pragma unroll
            for (int i = 0; i < 4; i++)
#pragma unroll
                for (int j = 0; j < 4; j++) mma16816(acc[i][j], X[i], Bf[j]);
#pragma unroll
            for (int j = 0; j < 4; j++) {
                const int r0 = (wn * 32 + j * 8 + g) * ROWB + cb;
                Bf[j][0] = *(const uint32_t*)(sBl + r0);
                Bf[j][1] = *(const uint32_t*)(sBl + r0 + 16);
            }
#pragma unroll
            for (int i = 0; i < 4; i++)
#pragma unroll
                for (int j = 0; j < 4; j++) mma16816(acc[i][j], Ahf[i], Bf[j]);
        }

        const int nf = it + NSTAGES - 1;
        if (nf < niter) issue_stage(nf % NSTAGES, nf * BK);
        asm volatile("cp.async.commit_group;");
    }

    // ---- epilogue
#pragma unroll
    for (int i = 0; i < 4; i++) {
        const int mrow = m0 + wm * 64 + i * 16 + g;
        const float rb0 = (BIAS_MODE == 2) ? bias[mrow]     : 0.f;
        const float rb1 = (BIAS_MODE == 2) ? bias[mrow + 8] : 0.f;
#pragma unroll
        for (int j = 0; j < 4; j++) {
            const int ncol = n0 + wn * 32 + j * 8 + tq * 2;
            float2 v0, v1;
            v0.x = alpha * acc[i][j][0];
            v0.y = alpha * acc[i][j][1];
            v1.x = alpha * acc[i][j][2];
            v1.y = alpha * acc[i][j][3];
            if (BIAS_MODE == 1) {
                const float b0 = bias[ncol], b1 = bias[ncol + 1];
                v0.x += b0; v0.y += b1;
                v1.x += b0; v1.y += b1;
            } else if (BIAS_MODE == 2) {
                v0.x += rb0; v0.y += rb0;
                v1.x += rb1; v1.y += rb1;
            }
            if (OUT_SPLIT) {
                __nv_bfloat162 h0, l0, h1, l1;
                h0.x = __float2bfloat16_rn(v0.x); l0.x = __float2bfloat16_rn(v0.x - __bfloat162float(h0.x));
                h0.y = __float2bfloat16_rn(v0.y); l0.y = __float2bfloat16_rn(v0.y - __bfloat162float(h0.y));
                h1.x = __float2bfloat16_rn(v1.x); l1.x = __float2bfloat16_rn(v1.x - __bfloat162float(h1.x));
                h1.y = __float2bfloat16_rn(v1.y); l1.y = __float2bfloat16_rn(v1.y - __bfloat162float(h1.y));
                *(__nv_bfloat162*)(Ch + (size_t)mrow * N + ncol)       = h0;
                *(__nv_bfloat162*)(Cl + (size_t)mrow * N + ncol)       = l0;
                *(__nv_bfloat162*)(Ch + (size_t)(mrow + 8) * N + ncol) = h1;
                *(__nv_bfloat162*)(Cl + (size_t)(mrow + 8) * N + ncol) = l1;
            } else {
                *(float2*)(C + (size_t)mrow * N + ncol)       = v0;
                *(float2*)(C + (size_t)(mrow + 8) * N + ncol) = v1;
            }
        }
    }
}

// ---------------- row softmax over N=8192, writes split bf16 P ----------------
__global__ void softmax_split_kernel(const float* __restrict__ S,
                                     bf16* __restrict__ Ph, bf16* __restrict__ Pl, int N)
{
    __shared__ float row[N_BANK];
    __shared__ float red[32];
    const int t = threadIdx.x;
    const size_t base = (size_t)blockIdx.x * N;

    float mx = -3.4e38f;
    for (int i = t; i < N; i += 256) {
        float v = S[base + i];
        row[i] = v;
        mx = fmaxf(mx, v);
    }
#pragma unroll
    for (int o = 16; o > 0; o >>= 1) mx = fmaxf(mx, __shfl_xor_sync(0xffffffffu, mx, o));
    if ((t & 31) == 0) red[t >> 5] = mx;
    __syncthreads();
    if (t == 0) {
        float m = red[0];
        for (int w = 1; w < 8; w++) m = fmaxf(m, red[w]);
        red[0] = m;
    }
    __syncthreads();
    mx = red[0];
    __syncthreads();

    float s = 0.f;
    for (int i = t; i < N; i += 256) {
        float e = __expf(row[i] - mx);
        row[i] = e;
        s += e;
    }
#pragma unroll
    for (int o = 16; o > 0; o >>= 1) s += __shfl_xor_sync(0xffffffffu, s, o);
    if ((t & 31) == 0) red[t >> 5] = s;
    __syncthreads();
    if (t == 0) {
        float m = 0.f;
        for (int w = 0; w < 8; w++) m += red[w];
        red[0] = m;
    }
    __syncthreads();
    const float inv = 1.f / red[0];
    for (int i = t; i < N; i += 256) {
        float p = row[i] * inv;
        bf16 h = __float2bfloat16_rn(p);
        bf16 l = __float2bfloat16_rn(p - __bfloat162float(h));
        Ph[base + i] = h;
        Pl[base + i] = l;
    }
}

// ---------------- cpair = f1*f2 -> LayerNorm -> PReLU -> split bf16 x ----------------
__global__ void gate_ln_prelu_kernel(const float* __restrict__ f1, const float* __restrict__ f2,
                                     const float* __restrict__ lnw, const float* __restrict__ lnb,
                                     const float* __restrict__ pa,
                                     bf16* __restrict__ xh, bf16* __restrict__ xl)
{
    const int t = threadIdx.x;
    const size_t base = (size_t)blockIdx.x * LATENT;
    __shared__ float redA[32];
    __shared__ float redB[32];

    float c[4];
    float sum = 0.f, ss = 0.f;
#pragma unroll
    for (int j = 0; j < 4; j++) {
        const int col = t + j * 256;
        float v = f1[base + col] * f2[base + col];
        c[j] = v;
        sum += v;
        ss += v * v;
    }
#pragma unroll
    for (int o = 16; o > 0; o >>= 1) {
        sum += __shfl_xor_sync(0xffffffffu, sum, o);
        ss  += __shfl_xor_sync(0xffffffffu, ss,  o);
    }
    if ((t & 31) == 0) { redA[t >> 5] = sum; redB[t >> 5] = ss; }
    __syncthreads();
    if (t == 0) {
        float a = 0.f, b = 0.f;
        for (int w = 0; w < 8; w++) { a += redA[w]; b += redB[w]; }
        redA[0] = a; redB[0] = b;
    }
    __syncthreads();
    const float mu   = redA[0] * (1.f / LATENT);
    const float var  = redB[0] * (1.f / LATENT) - mu * mu;
    const float rstd = rsqrtf(var + 1e-5f);
    const float a    = pa[0];
#pragma unroll
    for (int j = 0; j < 4; j++) {
        const int col = t + j * 256;
        float v = (c[j] - mu) * rstd * lnw[col] + lnb[col];
        v = v >= 0.f ? v : a * v;
        bf16 h = __float2bfloat16_rn(v);
        bf16 l = __float2bfloat16_rn(v - __bfloat162float(h));
        xh[base + col] = h;
        xl[base + col] = l;
    }
}

// ---------------- launch ----------------
static inline void* sym(const void* s) { void* p; cudaGetSymbolAddress(&p, s); return p; }

extern "C" void kernel_launch(void* const* d_in, const int* in_sizes, int n_in,
                              void* d_out, int out_size)
{
    const float* feat = (const float*)d_in[0];
    const float* bank = (const float*)d_in[1];
    const float* Wc1 = (const float*)d_in[2];  const float* bc1 = (const float*)d_in[3];
    const float* Wc2 = (const float*)d_in[4];  const float* bc2 = (const float*)d_in[5];
    const float* Wc3 = (const float*)d_in[6];  const float* bc3 = (const float*)d_in[7];
    const float* Wd1 = (const float*)d_in[8];  const float* bd1 = (const float*)d_in[9];
    const float* Wd2 = (const float*)d_in[10]; const float* bd2 = (const float*)d_in[11];
    const float* Wd3 = (const float*)d_in[12]; const float* bd3 = (const float*)d_in[13];
    const float* lnw = (const float*)d_in[14]; const float* lnb = (const float*)d_in[15];
    const float* pa  = (const float*)d_in[16];
    const float* Wffn = (const float*)d_in[17]; const float* bffn = (const float*)d_in[18];
    float* out = (float*)d_out;

    bf16 *feath = (bf16*)sym(g_feath), *featl = (bf16*)sym(g_featl);
    bf16 *bankh = (bf16*)sym(g_bankh), *bankl = (bf16*)sym(g_bankl);
    bf16 *wc1h = (bf16*)sym(g_wc1h), *wc1l = (bf16*)sym(g_wc1l);
    bf16 *wc2h = (bf16*)sym(g_wc2h), *wc2l = (bf16*)sym(g_wc2l);
    bf16 *wc3h = (bf16*)sym(g_wc3h), *wc3l = (bf16*)sym(g_wc3l);
    bf16 *wd1h = (bf16*)sym(g_wd1h), *wd1l = (bf16*)sym(g_wd1l);
    bf16 *wd2h = (bf16*)sym(g_wd2h), *wd2l = (bf16*)sym(g_wd2l);
    bf16 *wd3h = (bf16*)sym(g_wd3h), *wd3l = (bf16*)sym(g_wd3l);
    bf16 *wfh  = (bf16*)sym(g_wfh),  *wfl  = (bf16*)sym(g_wfl);
    bf16 *q1h = (bf16*)sym(g_q1h), *q1l = (bf16*)sym(g_q1l);
    bf16 *q2h = (bf16*)sym(g_q2h), *q2l = (bf16*)sym(g_q2l);
    bf16 *k1h = (bf16*)sym(g_k1h), *k1l = (bf16*)sym(g_k1l);
    bf16 *k2h = (bf16*)sym(g_k2h), *k2l = (bf16*)sym(g_k2l);
    bf16 *v1h = (bf16*)sym(g_v1h), *v1l = (bf16*)sym(g_v1l);
    bf16 *v2h = (bf16*)sym(g_v2h), *v2l = (bf16*)sym(g_v2l);
    float* S  = (float*)sym(g_S);
    bf16 *Ph = (bf16*)sym(g_Ph), *Pl = (bf16*)sym(g_Pl);
    float *f1 = (float*)sym(g_f1), *f2 = (float*)sym(g_f2);
    bf16 *xh = (bf16*)sym(g_xh), *xl = (bf16*)sym(g_xl);

    cudaFuncSetAttribute(gemm_bf<1, true>,  cudaFuncAttributeMaxDynamicSharedMemorySize, SMEM_TOTAL);
    cudaFuncSetAttribute(gemm_bf<2, true>,  cudaFuncAttributeMaxDynamicSharedMemorySize, SMEM_TOTAL);
    cudaFuncSetAttribute(gemm_bf<0, false>, cudaFuncAttributeMaxDynamicSharedMemorySize, SMEM_TOTAL);
    cudaFuncSetAttribute(gemm_bf<1, false>, cudaFuncAttributeMaxDynamicSharedMemorySize, SMEM_TOTAL);

    const dim3 blk(256);
    const float scale = 1.0f / 32.0f;

    // ---- pre-split harness inputs (fp32 -> hi/lo bf16)
    auto ps = [&](const float* src, bf16* h, bf16* l, int n) {
        presplit_kernel<<<(n / 4 + 255) / 256, 256>>>(src, h, l, n);
    };
    ps(feat, feath, featl, N_ROIS * QDIM);
    ps(bank, bankh, bankl, N_BANK * DIM_IN);
    ps(Wc1, wc1h, wc1l, LATENT * QDIM);
    ps(Wc2, wc2h, wc2l, LATENT * DIM_IN);
    ps(Wc3, wc3h, wc3l, LATENT * DIM_IN);
    ps(Wd1, wd1h, wd1l, LATENT * QDIM);
    ps(Wd2, wd2h, wd2l, LATENT * DIM_IN);
    ps(Wd3, wd3h, wd3l, LATENT * DIM_IN);
    ps(Wffn, wfh, wfl, DIM_IN * LATENT);

    // ---- projections (NT, split outputs)
    // q = feat @ W^T + b : [4096,1024]
    gemm_bf<1, true><<<dim3(LATENT/128, N_ROIS/128), blk, SMEM_TOTAL>>>(
        feath, featl, wc1h, wc1l, bc1, nullptr, q1h, q1l, N_ROIS, LATENT, QDIM, 1.f);
    gemm_bf<1, true><<<dim3(LATENT/128, N_ROIS/128), blk, SMEM_TOTAL>>>(
        feath, featl, wd1h, wd1l, bd1, nullptr, q2h, q2l, N_ROIS, LATENT, QDIM, 1.f);
    // k = bank @ W^T + b : [8192,1024]
    gemm_bf<1, true><<<dim3(LATENT/128, N_BANK/128), blk, SMEM_TOTAL>>>(
        bankh, bankl, wc2h, wc2l, bc2, nullptr, k1h, k1l, N_BANK, LATENT, DIM_IN, 1.f);
    gemm_bf<1, true><<<dim3(LATENT/128, N_BANK/128), blk, SMEM_TOTAL>>>(
        bankh, bankl, wd2h, wd2l, bd2, nullptr, k2h, k2l, N_BANK, LATENT, DIM_IN, 1.f);
    // vT = W @ bank^T + b(row) : [1024, 8192]
    gemm_bf<2, true><<<dim3(N_BANK/128, LATENT/128), blk, SMEM_TOTAL>>>(
        wc3h, wc3l, bankh, bankl, bc3, nullptr, v1h, v1l, LATENT, N_BANK, DIM_IN, 1.f);
    gemm_bf<2, true><<<dim3(N_BANK/128, LATENT/128), blk, SMEM_TOTAL>>>(
        wd3h, wd3l, bankh, bankl, bd3, nullptr, v2h, v2l, LATENT, N_BANK, DIM_IN, 1.f);

    // ---- branch 1: scores -> softmax(split) -> PV
    gemm_bf<0, false><<<dim3(N_BANK/128, N_ROIS/128), blk, SMEM_TOTAL>>>(
        q1h, q1l, k1h, k1l, nullptr, S, nullptr, nullptr, N_ROIS, N_BANK, LATENT, scale);
    softmax_split_kernel<<<N_ROIS, blk>>>(S, Ph, Pl, N_BANK);
    gemm_bf<0, false><<<dim3(LATENT/128, N_ROIS/128), blk, SMEM_TOTAL>>>(
        Ph, Pl, v1h, v1l, nullptr, f1, nullptr, nullptr, N_ROIS, LATENT, N_BANK, 1.f);

    // ---- branch 2
    gemm_bf<0, false><<<dim3(N_BANK/128, N_ROIS/128), blk, SMEM_TOTAL>>>(
        q2h, q2l, k2h, k2l, nullptr, S, nullptr, nullptr, N_ROIS, N_BANK, LATENT, scale);
    softmax_split_kernel<<<N_ROIS, blk>>>(S, Ph, Pl, N_BANK);
    gemm_bf<0, false><<<dim3(LATENT/128, N_ROIS/128), blk, SMEM_TOTAL>>>(
        Ph, Pl, v2h, v2l, nullptr, f2, nullptr, nullptr, N_ROIS, LATENT, N_BANK, 1.f);

    // ---- gate + LN + PReLU (writes split x)
    gate_ln_prelu_kernel<<<N_ROIS, blk>>>(f1, f2, lnw, lnb, pa, xh, xl);

    // ---- FFN -> out
    gemm_bf<1, false><<<dim3(DIM_IN/128, N_ROIS/128), blk, SMEM_TOTAL>>>(
        xh, xl, wfh, wfl, bffn, out, nullptr, nullptr, N_ROIS, DIM_IN, LATENT, 1.f);
}